// round 3
// baseline (speedup 1.0000x reference)
#include <cuda_runtime.h>
#include <cstdint>

#define BB 8
#define SS 1024
#define DD 768
#define HH 16
#define HD 48
#define TOK (BB*SS)          // 8192
#define BHN (BB*HH)          // 128

// Scratch (static device arrays — no allocation allowed)
__device__ __align__(256) float g_q[BHN*SS*HD];   // tf32-pre-rounded
__device__ __align__(256) float g_k[BHN*SS*HD];   // tf32-pre-rounded
__device__ __align__(256) float g_v[BHN*SS*HD];   // tf32-pre-rounded
__device__ __align__(256) float g_ao[TOK*DD];

// ---------------------------------------------------------------------------
__device__ __forceinline__ uint32_t f2tf(float x) {
    uint32_t u;
    asm("cvt.rna.tf32.f32 %0, %1;" : "=r"(u) : "f"(x));
    return u;
}

__device__ __forceinline__ void mma8(float c[4], const uint32_t a[4], const uint32_t b[2]) {
    asm volatile("mma.sync.aligned.m16n8k8.row.col.f32.tf32.tf32.f32 "
                 "{%0,%1,%2,%3}, {%4,%5,%6,%7}, {%8,%9}, {%0,%1,%2,%3};"
                 : "+f"(c[0]), "+f"(c[1]), "+f"(c[2]), "+f"(c[3])
                 : "r"(a[0]), "r"(a[1]), "r"(a[2]), "r"(a[3]),
                   "r"(b[0]), "r"(b[1]));
}

// ---------------------------------------------------------------------------
// GEMM core: C[128x128] tile of A[*,768] @ W[768,768]. (near legacy-tf32 peak)
// ---------------------------------------------------------------------------
__device__ __forceinline__ void gemm_core(const float* __restrict__ A,
                                          const float* __restrict__ W,
                                          uint32_t* As, uint32_t* Bs,
                                          float acc[4][4][4],
                                          int m0, int n0)
{
    const int tid  = threadIdx.x;
    const int lane = tid & 31, warp = tid >> 5;
    const int g = lane >> 2, tig = lane & 3;
    const int wm = (warp >> 2) * 64, wn = (warp & 3) * 32;

    for (int kt = 0; kt < DD / 32; ++kt) {
        const int k0c = kt * 32;
        #pragma unroll
        for (int it = 0; it < 4; ++it) {
            int f = tid + it * 256;
            int m = f >> 3, kq = f & 7;
            float4 v = *reinterpret_cast<const float4*>(
                &A[(size_t)(m0 + m) * DD + k0c + kq * 4]);
            uint4 w = make_uint4(f2tf(v.x), f2tf(v.y), f2tf(v.z), f2tf(v.w));
            *reinterpret_cast<uint4*>(&As[m * 36 + kq * 4]) = w;
        }
        #pragma unroll
        for (int it = 0; it < 4; ++it) {
            int f = tid + it * 256;
            int k = f >> 5, nq = f & 31;
            float4 v = *reinterpret_cast<const float4*>(
                &W[(size_t)(k0c + k) * DD + n0 + nq * 4]);
            uint4 w = make_uint4(f2tf(v.x), f2tf(v.y), f2tf(v.z), f2tf(v.w));
            *reinterpret_cast<uint4*>(&Bs[k * 136 + nq * 4]) = w;
        }
        __syncthreads();
        #pragma unroll
        for (int kk = 0; kk < 4; ++kk) {
            const int k0 = kk * 8;
            uint32_t a[4][4], b[4][2];
            #pragma unroll
            for (int mi = 0; mi < 4; ++mi) {
                int r = wm + mi * 16;
                a[mi][0] = As[(r + g) * 36     + k0 + tig];
                a[mi][1] = As[(r + g + 8) * 36 + k0 + tig];
                a[mi][2] = As[(r + g) * 36     + k0 + tig + 4];
                a[mi][3] = As[(r + g + 8) * 36 + k0 + tig + 4];
            }
            #pragma unroll
            for (int ni = 0; ni < 4; ++ni) {
                int c = wn + ni * 8 + g;
                b[ni][0] = Bs[(k0 + tig) * 136     + c];
                b[ni][1] = Bs[(k0 + tig + 4) * 136 + c];
            }
            #pragma unroll
            for (int mi = 0; mi < 4; ++mi)
                #pragma unroll
                for (int ni = 0; ni < 4; ++ni)
                    mma8(acc[mi][ni], a[mi], b[ni]);
        }
        __syncthreads();
    }
}

// ---------------------------------------------------------------------------
// QKV projection; outputs tf32-pre-rounded, remapped to [B*H, S, 48]
// ---------------------------------------------------------------------------
__global__ void __launch_bounds__(256, 2)
qkv_kernel(const float* __restrict__ x,
           const float* __restrict__ Wq, const float* __restrict__ bq,
           const float* __restrict__ Wk, const float* __restrict__ bk,
           const float* __restrict__ Wv, const float* __restrict__ bv)
{
    __shared__ uint32_t As[128 * 36];
    __shared__ uint32_t Bs[32 * 136];
    const int z = blockIdx.z;
    const float* W    = (z == 0) ? Wq : (z == 1) ? Wk : Wv;
    const float* bias = (z == 0) ? bq : (z == 1) ? bk : bv;
    float* out        = (z == 0) ? g_q : (z == 1) ? g_k : g_v;

    float acc[4][4][4] = {};
    const int m0 = blockIdx.x * 128, n0 = blockIdx.y * 128;
    gemm_core(x, W, As, Bs, acc, m0, n0);

    const int lane = threadIdx.x & 31, warp = threadIdx.x >> 5;
    const int g = lane >> 2, tig = lane & 3;
    const int wm = (warp >> 2) * 64, wn = (warp & 3) * 32;
    #pragma unroll
    for (int mi = 0; mi < 4; ++mi)
        #pragma unroll
        for (int ni = 0; ni < 4; ++ni)
            #pragma unroll
            for (int e = 0; e < 4; ++e) {
                int r = wm + mi * 16 + g + ((e >= 2) ? 8 : 0);
                int c = n0 + wn + ni * 8 + 2 * tig + (e & 1);
                int t = m0 + r;
                int bb = t >> 10, s = t & 1023;
                int h = c / HD, hd = c % HD;
                out[(((size_t)(bb * HH + h)) * SS + s) * HD + hd] =
                    __uint_as_float(f2tf(acc[mi][ni][e] + bias[c]));
            }
}

// ---------------------------------------------------------------------------
__global__ void __launch_bounds__(256, 2)
oproj_kernel(const float* __restrict__ Wo, const float* __restrict__ bo,
             float* __restrict__ out)
{
    __shared__ uint32_t As[128 * 36];
    __shared__ uint32_t Bs[32 * 136];
    float acc[4][4][4] = {};
    const int m0 = blockIdx.x * 128, n0 = blockIdx.y * 128;
    gemm_core(g_ao, Wo, As, Bs, acc, m0, n0);

    const int lane = threadIdx.x & 31, warp = threadIdx.x >> 5;
    const int g = lane >> 2, tig = lane & 3;
    const int wm = (warp >> 2) * 64, wn = (warp & 3) * 32;
    #pragma unroll
    for (int mi = 0; mi < 4; ++mi)
        #pragma unroll
        for (int ni = 0; ni < 4; ++ni)
            #pragma unroll
            for (int e = 0; e < 4; ++e) {
                int r = m0 + wm + mi * 16 + g + ((e >= 2) ? 8 : 0);
                int c = n0 + wn + ni * 8 + 2 * tig + (e & 1);
                out[(size_t)r * DD + c] = acc[mi][ni][e] + bo[c];
            }
}

// ---------------------------------------------------------------------------
// Flash attention, q-tile 128, 8 warps, warp = 16 rows x full width.
// In-register online softmax (no cross-warp stats, no smem stat arrays).
//   Qs[128][52]  Ks[64][52]  Vs[64][56]  Ps[128][68]   (conflict-free pads)
// 2 __syncthreads per k-tile.
// ---------------------------------------------------------------------------
#define QSP 52
#define VSP 56
#define PSP 68

__global__ void __launch_bounds__(256, 2)
attn_kernel()
{
    extern __shared__ float sm[];
    float* Qs = sm;                  // 128*52
    float* Ks = Qs + 128 * QSP;      // 64*52
    float* Vs = Ks + 64 * QSP;       // 64*56
    float* Ps = Vs + 64 * VSP;       // 128*68

    const int tid  = threadIdx.x;
    const int lane = tid & 31, warp = tid >> 5;
    const int g = lane >> 2, tig = lane & 3;
    const int bh = blockIdx.y, q0 = blockIdx.x * 128;
    const float* qp = g_q + (size_t)bh * SS * HD;
    const float* kp = g_k + (size_t)bh * SS * HD;
    const float* vp = g_v + (size_t)bh * SS * HD;

    // Load Q tile (already tf32-rounded in gmem): 128x48, 24 floats/thread
    {
        const int r = tid >> 1, c0 = (tid & 1) * 24;
        const float* src = qp + (size_t)(q0 + r) * HD + c0;
        #pragma unroll
        for (int j = 0; j < 6; ++j)
            *reinterpret_cast<float4*>(&Qs[r * QSP + c0 + j * 4]) =
                *reinterpret_cast<const float4*>(src + j * 4);
    }

    const int wr = warp * 16;        // warp's row base within tile
    const int kvr = tid >> 2, kvc = (tid & 3) * 12;

    float o[6][4] = {};
    float m0 = -1e30f, m1 = -1e30f, l0 = 0.f, l1 = 0.f;
    const float sc = 0.14433756729740643f;   // 1/sqrt(48)

    for (int kt = 0; kt < SS / 64; ++kt) {
        // Load K,V tiles: 64x48 each, 12 floats/thread each
        {
            const float* ks = kp + (size_t)(kt * 64 + kvr) * HD + kvc;
            const float* vs = vp + (size_t)(kt * 64 + kvr) * HD + kvc;
            #pragma unroll
            for (int j = 0; j < 3; ++j)
                *reinterpret_cast<float4*>(&Ks[kvr * QSP + kvc + j * 4]) =
                    *reinterpret_cast<const float4*>(ks + j * 4);
            #pragma unroll
            for (int j = 0; j < 3; ++j)
                *reinterpret_cast<float4*>(&Vs[kvr * VSP + kvc + j * 4]) =
                    *reinterpret_cast<const float4*>(vs + j * 4);
        }
        __syncthreads();

        // Scores: warp computes rows wr..wr+15 x all 64 cols
        float s[8][4] = {};
        #pragma unroll
        for (int d0 = 0; d0 < 48; d0 += 8) {
            uint32_t a[4];
            a[0] = __float_as_uint(Qs[(wr + g) * QSP     + d0 + tig]);
            a[1] = __float_as_uint(Qs[(wr + g + 8) * QSP + d0 + tig]);
            a[2] = __float_as_uint(Qs[(wr + g) * QSP     + d0 + tig + 4]);
            a[3] = __float_as_uint(Qs[(wr + g + 8) * QSP + d0 + tig + 4]);
            #pragma unroll
            for (int nb = 0; nb < 8; ++nb) {
                uint32_t b[2];
                int c = nb * 8 + g;
                b[0] = __float_as_uint(Ks[c * QSP + d0 + tig]);
                b[1] = __float_as_uint(Ks[c * QSP + d0 + tig + 4]);
                mma8(s[nb], a, b);
            }
        }

        // In-register online softmax (rows g and g+8 of this warp)
        float mx0 = -1e30f, mx1 = -1e30f;
        #pragma unroll
        for (int nb = 0; nb < 8; ++nb) {
            mx0 = fmaxf(mx0, fmaxf(s[nb][0], s[nb][1]));
            mx1 = fmaxf(mx1, fmaxf(s[nb][2], s[nb][3]));
        }
        mx0 = fmaxf(mx0, __shfl_xor_sync(0xffffffffu, mx0, 1));
        mx0 = fmaxf(mx0, __shfl_xor_sync(0xffffffffu, mx0, 2));
        mx1 = fmaxf(mx1, __shfl_xor_sync(0xffffffffu, mx1, 1));
        mx1 = fmaxf(mx1, __shfl_xor_sync(0xffffffffu, mx1, 2));
        const float mn0 = fmaxf(m0, mx0), mn1 = fmaxf(m1, mx1);
        const float corr0 = __expf((m0 - mn0) * sc);
        const float corr1 = __expf((m1 - mn1) * sc);
        m0 = mn0; m1 = mn1;

        float sum0 = 0.f, sum1 = 0.f;
        #pragma unroll
        for (int nb = 0; nb < 8; ++nb) {
            float p0 = __expf((s[nb][0] - mn0) * sc);
            float p1 = __expf((s[nb][1] - mn0) * sc);
            float p2 = __expf((s[nb][2] - mn1) * sc);
            float p3 = __expf((s[nb][3] - mn1) * sc);
            sum0 += p0 + p1; sum1 += p2 + p3;
            float2 w0 = make_float2(__uint_as_float(f2tf(p0)),
                                    __uint_as_float(f2tf(p1)));
            float2 w1 = make_float2(__uint_as_float(f2tf(p2)),
                                    __uint_as_float(f2tf(p3)));
            *reinterpret_cast<float2*>(&Ps[(wr + g) * PSP + nb * 8 + 2 * tig]) = w0;
            *reinterpret_cast<float2*>(&Ps[(wr + g + 8) * PSP + nb * 8 + 2 * tig]) = w1;
        }
        sum0 += __shfl_xor_sync(0xffffffffu, sum0, 1);
        sum0 += __shfl_xor_sync(0xffffffffu, sum0, 2);
        sum1 += __shfl_xor_sync(0xffffffffu, sum1, 1);
        sum1 += __shfl_xor_sync(0xffffffffu, sum1, 2);
        l0 = l0 * corr0 + sum0;
        l1 = l1 * corr1 + sum1;

        // Rescale O fragments
        #pragma unroll
        for (int nb = 0; nb < 6; ++nb) {
            o[nb][0] *= corr0; o[nb][1] *= corr0;
            o[nb][2] *= corr1; o[nb][3] *= corr1;
        }
        __syncwarp();   // P visible to all lanes of this warp

        // PV: warp's 16 rows x 48 cols, K=64
        #pragma unroll
        for (int k0 = 0; k0 < 64; k0 += 8) {
            uint32_t a[4];
            a[0] = __float_as_uint(Ps[(wr + g) * PSP     + k0 + tig]);
            a[1] = __float_as_uint(Ps[(wr + g + 8) * PSP + k0 + tig]);
            a[2] = __float_as_uint(Ps[(wr + g) * PSP     + k0 + tig + 4]);
            a[3] = __float_as_uint(Ps[(wr + g + 8) * PSP + k0 + tig + 4]);
            #pragma unroll
            for (int nb = 0; nb < 6; ++nb) {
                uint32_t b[2];
                int c = nb * 8 + g;
                b[0] = __float_as_uint(Vs[(k0 + tig) * VSP     + c]);
                b[1] = __float_as_uint(Vs[(k0 + tig + 4) * VSP + c]);
                mma8(o[nb], a, b);
            }
        }
        __syncthreads();   // Vs/Ks consumed before next tile overwrites
    }

    // Epilogue: normalize, scatter to g_ao [B*S, 768]
    const float li0 = 1.f / l0, li1 = 1.f / l1;
    const int bb = bh >> 4, h = bh & 15;
    const int r0 = q0 + wr + g, r1 = r0 + 8;
    #pragma unroll
    for (int nb = 0; nb < 6; ++nb) {
        int c = h * HD + nb * 8 + 2 * tig;
        float* p0 = g_ao + ((size_t)(bb * SS + r0)) * DD + c;
        float* p1 = g_ao + ((size_t)(bb * SS + r1)) * DD + c;
        p0[0] = o[nb][0] * li0; p0[1] = o[nb][1] * li0;
        p1[0] = o[nb][2] * li1; p1[1] = o[nb][3] * li1;
    }
}

// ---------------------------------------------------------------------------
extern "C" void kernel_launch(void* const* d_in, const int* in_sizes, int n_in,
                              void* d_out, int out_size)
{
    const float* x  = (const float*)d_in[0];
    const float* Wq = (const float*)d_in[1];
    const float* bq = (const float*)d_in[2];
    const float* Wk = (const float*)d_in[3];
    const float* bk = (const float*)d_in[4];
    const float* Wv = (const float*)d_in[5];
    const float* bv = (const float*)d_in[6];
    const float* Wo = (const float*)d_in[7];
    const float* bo = (const float*)d_in[8];
    float* out = (float*)d_out;

    static const size_t attn_smem =
        (128 * QSP + 64 * QSP + 64 * VSP + 128 * PSP) * sizeof(float);
    cudaFuncSetAttribute(attn_kernel,
                         cudaFuncAttributeMaxDynamicSharedMemorySize,
                         (int)attn_smem);

    dim3 gq(TOK / 128, DD / 128, 3);
    qkv_kernel<<<gq, 256>>>(x, Wq, bq, Wk, bk, Wv, bv);

    dim3 ga(SS / 128, BHN);
    attn_kernel<<<ga, 256, attn_smem>>>();

    dim3 go(TOK / 128, DD / 128);
    oproj_kernel<<<go, 256>>>(Wo, bo, out);
}

// round 5
// speedup vs baseline: 2.7208x; 2.7208x over previous
#include <cuda_runtime.h>
#include <cuda_fp16.h>
#include <cstdint>

#define BB 8
#define SS 1024
#define DD 768
#define HH 16
#define HD 48
#define TOK (BB*SS)          // 8192
#define BHN (BB*HH)          // 128

// Static scratch (half precision)
__device__ __align__(256) __half g_xh[TOK*DD];
__device__ __align__(256) __half g_wh[4][DD*DD];     // Wq,Wk,Wv,Wo
__device__ __align__(256) __half g_qh[BHN*SS*HD];
__device__ __align__(256) __half g_kh[BHN*SS*HD];
__device__ __align__(256) __half g_vh[BHN*SS*HD];
__device__ __align__(256) __half g_aoh[TOK*DD];

// ---------------------------------------------------------------------------
// PTX helpers
// ---------------------------------------------------------------------------
__device__ __forceinline__ void ldm_x4(uint32_t r[4], const __half* p) {
    uint32_t a = (uint32_t)__cvta_generic_to_shared(p);
    asm volatile("ldmatrix.sync.aligned.m8n8.x4.shared.b16 {%0,%1,%2,%3}, [%4];"
                 : "=r"(r[0]), "=r"(r[1]), "=r"(r[2]), "=r"(r[3]) : "r"(a));
}
__device__ __forceinline__ void ldm_x4t(uint32_t r[4], const __half* p) {
    uint32_t a = (uint32_t)__cvta_generic_to_shared(p);
    asm volatile("ldmatrix.sync.aligned.m8n8.x4.trans.shared.b16 {%0,%1,%2,%3}, [%4];"
                 : "=r"(r[0]), "=r"(r[1]), "=r"(r[2]), "=r"(r[3]) : "r"(a));
}
__device__ __forceinline__ void mma16(float c[4], const uint32_t a[4],
                                      uint32_t b0, uint32_t b1) {
    asm volatile("mma.sync.aligned.m16n8k16.row.col.f32.f16.f16.f32 "
                 "{%0,%1,%2,%3}, {%4,%5,%6,%7}, {%8,%9}, {%0,%1,%2,%3};"
                 : "+f"(c[0]), "+f"(c[1]), "+f"(c[2]), "+f"(c[3])
                 : "r"(a[0]), "r"(a[1]), "r"(a[2]), "r"(a[3]), "r"(b0), "r"(b1));
}
__device__ __forceinline__ void cpa16(__half* dst, const __half* src) {
    uint32_t d = (uint32_t)__cvta_generic_to_shared(dst);
    asm volatile("cp.async.cg.shared.global [%0], [%1], 16;" :: "r"(d), "l"(src));
}
#define CP_COMMIT() asm volatile("cp.async.commit_group;")
#define CP_WAIT(N)  asm volatile("cp.async.wait_group %0;" :: "n"(N))

// ---------------------------------------------------------------------------
// Prep: convert x and the 4 weight matrices to half (rn rounding)
// ---------------------------------------------------------------------------
__global__ void prep_kernel(const float* __restrict__ x,
                            const float* __restrict__ Wq, const float* __restrict__ Wk,
                            const float* __restrict__ Wv, const float* __restrict__ Wo)
{
    const int y = blockIdx.y;
    const float* src; __half* dst; int n;
    if (y == 0)      { src = x;  dst = g_xh;     n = TOK * DD; }
    else             { src = (y == 1) ? Wq : (y == 2) ? Wk : (y == 3) ? Wv : Wo;
                       dst = g_wh[y - 1];        n = DD * DD; }
    int idx = (blockIdx.x * 256 + threadIdx.x) * 4;
    if (idx < n) {
        float4 v = *reinterpret_cast<const float4*>(src + idx);
        __half2 h0 = __floats2half2_rn(v.x, v.y);
        __half2 h1 = __floats2half2_rn(v.z, v.w);
        *reinterpret_cast<__half2*>(dst + idx)     = h0;
        *reinterpret_cast<__half2*>(dst + idx + 2) = h1;
    }
}

// ---------------------------------------------------------------------------
// fp16 GEMM core: C[128x128] = A[*,768] @ W[768,768]. 256 thr = 8 warps.
// Warp tile 64x32. BK=32 (2 k16 steps). cp.async double buffer.
// As stride 40 halfs (80B = 5*16B), Bs stride 136 halfs (272B = 17*16B).
// ---------------------------------------------------------------------------
struct GemmSmem {
    __half As[2][128 * 40];
    __half Bs[2][32 * 136];
};

__device__ __forceinline__ void gemm_load(GemmSmem* s, int buf,
                                          const __half* __restrict__ A,
                                          const __half* __restrict__ W,
                                          int m0, int n0, int kt)
{
    const int tid = threadIdx.x;
    const int k0c = kt * 32;
    // A: 128 rows x 32 halfs = 512 x 16B chunks; 2 per thread
    #pragma unroll
    for (int i = 0; i < 2; ++i) {
        int idx = tid + i * 256;
        int row = idx >> 2, cc = (idx & 3) * 8;
        cpa16(&s->As[buf][row * 40 + cc],
              &A[(size_t)(m0 + row) * DD + k0c + cc]);
    }
    // B: 32 rows x 128 halfs = 512 x 16B chunks; 2 per thread  (R4 bug: was 1)
    #pragma unroll
    for (int i = 0; i < 2; ++i) {
        int idx = tid + i * 256;
        int row = idx >> 4, cc = (idx & 15) * 8;
        cpa16(&s->Bs[buf][row * 136 + cc],
              &W[(size_t)(k0c + row) * DD + n0 + cc]);
    }
}

__device__ __forceinline__ void gemm_compute(GemmSmem* s, int buf,
                                             float acc[4][4][4])
{
    const int lane = threadIdx.x & 31, warp = threadIdx.x >> 5;
    const int wm = (warp >> 2) * 64, wn = (warp & 3) * 32;
    const int lr  = lane & 7;
    const int lk8 = ((lane >> 3) & 1) * 8;
    const int lh8 = (lane >> 4) * 8;
    #pragma unroll
    for (int ks = 0; ks < 2; ++ks) {
        const int k0 = ks * 16;
        uint32_t a[4][4], b[2][4];
        #pragma unroll
        for (int mi = 0; mi < 4; ++mi)
            ldm_x4(a[mi], &s->As[buf][(wm + mi * 16 + lr + lk8) * 40 + k0 + lh8]);
        #pragma unroll
        for (int nh = 0; nh < 2; ++nh)
            ldm_x4t(b[nh], &s->Bs[buf][(k0 + lr + lk8) * 136 + wn + nh * 16 + lh8]);
        #pragma unroll
        for (int mi = 0; mi < 4; ++mi)
            #pragma unroll
            for (int ni = 0; ni < 4; ++ni)
                mma16(acc[mi][ni], a[mi], b[ni >> 1][(ni & 1) * 2],
                      b[ni >> 1][(ni & 1) * 2 + 1]);
    }
}

#define GEMM_LOOP(Aptr, Wptr)                                            \
    gemm_load(sm, 0, Aptr, Wptr, m0, n0, 0);                             \
    CP_COMMIT();                                                         \
    for (int kt = 0; kt < DD / 32; ++kt) {                               \
        if (kt < DD / 32 - 1) {                                          \
            gemm_load(sm, (kt + 1) & 1, Aptr, Wptr, m0, n0, kt + 1);     \
            CP_COMMIT(); CP_WAIT(1);                                     \
        } else CP_WAIT(0);                                               \
        __syncthreads();                                                 \
        gemm_compute(sm, kt & 1, acc);                                   \
        __syncthreads();                                                 \
    }

// ---------------------------------------------------------------------------
// QKV projection -> g_qh/g_kh/g_vh as [B*H][S][48] half
// ---------------------------------------------------------------------------
__global__ void __launch_bounds__(256, 2)
qkv_kernel(const float* __restrict__ bq, const float* __restrict__ bk,
           const float* __restrict__ bv)
{
    __shared__ GemmSmem smem;
    GemmSmem* sm = &smem;
    const int z = blockIdx.z;
    const __half* W    = g_wh[z];
    const float* bias  = (z == 0) ? bq : (z == 1) ? bk : bv;
    __half* out        = (z == 0) ? g_qh : (z == 1) ? g_kh : g_vh;

    float acc[4][4][4] = {};
    const int m0 = blockIdx.x * 128, n0 = blockIdx.y * 128;
    GEMM_LOOP(g_xh, W)

    const int lane = threadIdx.x & 31, warp = threadIdx.x >> 5;
    const int g = lane >> 2, tig = lane & 3;
    const int wm = (warp >> 2) * 64, wn = (warp & 3) * 32;
    #pragma unroll
    for (int mi = 0; mi < 4; ++mi)
        #pragma unroll
        for (int ni = 0; ni < 4; ++ni) {
            const int c = n0 + wn + ni * 8 + 2 * tig;
            const int h = c / HD, hd = c % HD;
            const float b0f = bias[c], b1f = bias[c + 1];
            #pragma unroll
            for (int half_row = 0; half_row < 2; ++half_row) {
                int r = wm + mi * 16 + g + half_row * 8;
                int t = m0 + r;
                int bb = t >> 10, ss = t & 1023;
                __half2 hv = __floats2half2_rn(acc[mi][ni][half_row * 2] + b0f,
                                               acc[mi][ni][half_row * 2 + 1] + b1f);
                *reinterpret_cast<__half2*>(
                    &out[(((size_t)(bb * HH + h)) * SS + ss) * HD + hd]) = hv;
            }
        }
}

// ---------------------------------------------------------------------------
// Output projection: g_aoh @ Wo + bo -> d_out (fp32)
// ---------------------------------------------------------------------------
__global__ void __launch_bounds__(256, 2)
oproj_kernel(const float* __restrict__ bo, float* __restrict__ out)
{
    __shared__ GemmSmem smem;
    GemmSmem* sm = &smem;
    float acc[4][4][4] = {};
    const int m0 = blockIdx.x * 128, n0 = blockIdx.y * 128;
    GEMM_LOOP(g_aoh, g_wh[3])

    const int lane = threadIdx.x & 31, warp = threadIdx.x >> 5;
    const int g = lane >> 2, tig = lane & 3;
    const int wm = (warp >> 2) * 64, wn = (warp & 3) * 32;
    #pragma unroll
    for (int mi = 0; mi < 4; ++mi)
        #pragma unroll
        for (int ni = 0; ni < 4; ++ni) {
            const int c = n0 + wn + ni * 8 + 2 * tig;
            const float b0f = bo[c], b1f = bo[c + 1];
            #pragma unroll
            for (int half_row = 0; half_row < 2; ++half_row) {
                int r = m0 + wm + mi * 16 + g + half_row * 8;
                float2 v = make_float2(acc[mi][ni][half_row * 2] + b0f,
                                       acc[mi][ni][half_row * 2 + 1] + b1f);
                *reinterpret_cast<float2*>(&out[(size_t)r * DD + c]) = v;
            }
        }
}

// ---------------------------------------------------------------------------
// Flash attention, fp16 mma. CTA = 128 thr (4 warps), q-tile 64, k-tile 64.
// Warp owns 16 rows x full width -> in-register online softmax.
// Qs/Ks/Vs stride 56 halfs (112B=7*16B), Ps stride 72 halfs (144B=9*16B).
// cp.async double-buffered K/V. 44KB static smem -> 4 CTAs/SM.
// ---------------------------------------------------------------------------
__global__ void __launch_bounds__(128, 4)
attn_kernel()
{
    __shared__ __half Qs[64 * 56];
    __shared__ __half Ks[2][64 * 56];
    __shared__ __half Vs[2][64 * 56];
    __shared__ __half Ps[64 * 72];

    const int tid  = threadIdx.x;
    const int lane = tid & 31, warp = tid >> 5;
    const int g = lane >> 2, tig = lane & 3;
    const int bh = blockIdx.y, q0 = blockIdx.x * 64;
    const __half* qp = g_qh + (size_t)bh * SS * HD;
    const __half* kp = g_kh + (size_t)bh * SS * HD;
    const __half* vp = g_vh + (size_t)bh * SS * HD;

    // cp.async layout: thread t -> row t>>1, half-row (t&1)*24, 3 x 16B
    const int lrow = tid >> 1, lo = (tid & 1) * 24;

    // Prologue: Q + K0 + V0
    #pragma unroll
    for (int j = 0; j < 3; ++j)
        cpa16(&Qs[lrow * 56 + lo + 8 * j],
              &qp[(size_t)(q0 + lrow) * HD + lo + 8 * j]);
    #pragma unroll
    for (int j = 0; j < 3; ++j)
        cpa16(&Ks[0][lrow * 56 + lo + 8 * j],
              &kp[(size_t)lrow * HD + lo + 8 * j]);
    #pragma unroll
    for (int j = 0; j < 3; ++j)
        cpa16(&Vs[0][lrow * 56 + lo + 8 * j],
              &vp[(size_t)lrow * HD + lo + 8 * j]);
    CP_COMMIT();

    const int wr  = warp * 16;
    const int lr  = lane & 7;
    const int lk8 = ((lane >> 3) & 1) * 8;
    const int lh8 = (lane >> 4) * 8;

    float o[6][4] = {};
    float mr0 = -1e30f, mr1 = -1e30f, l0 = 0.f, l1 = 0.f;
    const float sc = 0.14433756729740643f;   // 1/sqrt(48)

    for (int kt = 0; kt < SS / 64; ++kt) {
        if (kt < SS / 64 - 1) {
            const int nb = (kt + 1) & 1;
            const size_t base = (size_t)((kt + 1) * 64 + lrow) * HD + lo;
            #pragma unroll
            for (int j = 0; j < 3; ++j)
                cpa16(&Ks[nb][lrow * 56 + lo + 8 * j], &kp[base + 8 * j]);
            #pragma unroll
            for (int j = 0; j < 3; ++j)
                cpa16(&Vs[nb][lrow * 56 + lo + 8 * j], &vp[base + 8 * j]);
            CP_COMMIT(); CP_WAIT(1);
        } else CP_WAIT(0);
        __syncthreads();

        const __half* Kb = Ks[kt & 1];
        const __half* Vb = Vs[kt & 1];

        // Scores: warp rows wr..wr+15 x 64 cols, K=48 (3 k16-steps)
        float s[8][4] = {};
        #pragma unroll
        for (int ks = 0; ks < 3; ++ks) {
            const int k0 = ks * 16;
            uint32_t a[4];
            ldm_x4(a, &Qs[(wr + lr + lk8) * 56 + k0 + lh8]);
            #pragma unroll
            for (int nh = 0; nh < 4; ++nh) {
                uint32_t b[4];
                ldm_x4(b, &Kb[(nh * 16 + lr + (lane >> 4) * 8) * 56 + k0 + lk8]);
                mma16(s[2 * nh],     a, b[0], b[1]);
                mma16(s[2 * nh + 1], a, b[2], b[3]);
            }
        }

        // In-register online softmax (rows g, g+8 of this warp)
        float mx0 = -1e30f, mx1 = -1e30f;
        #pragma unroll
        for (int nb = 0; nb < 8; ++nb) {
            mx0 = fmaxf(mx0, fmaxf(s[nb][0], s[nb][1]));
            mx1 = fmaxf(mx1, fmaxf(s[nb][2], s[nb][3]));
        }
        mx0 = fmaxf(mx0, __shfl_xor_sync(0xffffffffu, mx0, 1));
        mx0 = fmaxf(mx0, __shfl_xor_sync(0xffffffffu, mx0, 2));
        mx1 = fmaxf(mx1, __shfl_xor_sync(0xffffffffu, mx1, 1));
        mx1 = fmaxf(mx1, __shfl_xor_sync(0xffffffffu, mx1, 2));
        const float mn0 = fmaxf(mr0, mx0), mn1 = fmaxf(mr1, mx1);
        const float corr0 = __expf((mr0 - mn0) * sc);
        const float corr1 = __expf((mr1 - mn1) * sc);
        mr0 = mn0; mr1 = mn1;

        float sum0 = 0.f, sum1 = 0.f;
        #pragma unroll
        for (int nb = 0; nb < 8; ++nb) {
            float p0 = __expf((s[nb][0] - mn0) * sc);
            float p1 = __expf((s[nb][1] - mn0) * sc);
            float p2 = __expf((s[nb][2] - mn1) * sc);
            float p3 = __expf((s[nb][3] - mn1) * sc);
            sum0 += p0 + p1; sum1 += p2 + p3;
            *reinterpret_cast<__half2*>(&Ps[(wr + g) * 72 + nb * 8 + 2 * tig]) =
                __floats2half2_rn(p0, p1);
            *reinterpret_cast<__half2*>(&Ps[(wr + g + 8) * 72 + nb * 8 + 2 * tig]) =
                __floats2half2_rn(p2, p3);
        }
        sum0 += __shfl_xor_sync(0xffffffffu, sum0, 1);
        sum0 += __shfl_xor_sync(0xffffffffu, sum0, 2);
        sum1 += __shfl_xor_sync(0xffffffffu, sum1, 1);
        sum1 += __shfl_xor_sync(0xffffffffu, sum1, 2);
        l0 = l0 * corr0 + sum0;
        l1 = l1 * corr1 + sum1;

        #pragma unroll
        for (int nb = 0; nb < 6; ++nb) {
            o[nb][0] *= corr0; o[nb][1] *= corr0;
            o[nb][2] *= corr1; o[nb][3] *= corr1;
        }
        __syncwarp();   // P visible within warp

        // PV: warp rows x 48 cols, K=64 (4 k16-steps)
        #pragma unroll
        for (int ks = 0; ks < 4; ++ks) {
            const int k0 = ks * 16;
            uint32_t a[4];
            ldm_x4(a, &Ps[(wr + lr + lk8) * 72 + k0 + lh8]);
            #pragma unroll
            for (int nh = 0; nh < 3; ++nh) {
                uint32_t b[4];
                ldm_x4t(b, &Vb[(k0 + lr + lk8) * 56 + nh * 16 + lh8]);
                mma16(o[2 * nh],     a, b[0], b[1]);
                mma16(o[2 * nh + 1], a, b[2], b[3]);
            }
        }
        __syncthreads();
    }

    // Epilogue: normalize, convert to half, write g_aoh [B*S][768]
    const float li0 = 1.f / l0, li1 = 1.f / l1;
    const int bb = bh >> 4, h = bh & 15;
    const int r0 = q0 + wr + g, r1 = r0 + 8;
    #pragma unroll
    for (int nb = 0; nb < 6; ++nb) {
        int c = h * HD + nb * 8 + 2 * tig;
        *reinterpret_cast<__half2*>(&g_aoh[((size_t)(bb * SS + r0)) * DD + c]) =
            __floats2half2_rn(o[nb][0] * li0, o[nb][1] * li0);
        *reinterpret_cast<__half2*>(&g_aoh[((size_t)(bb * SS + r1)) * DD + c]) =
            __floats2half2_rn(o[nb][2] * li1, o[nb][3] * li1);
    }
}

// ---------------------------------------------------------------------------
extern "C" void kernel_launch(void* const* d_in, const int* in_sizes, int n_in,
                              void* d_out, int out_size)
{
    const float* x  = (const float*)d_in[0];
    const float* Wq = (const float*)d_in[1];
    const float* bq = (const float*)d_in[2];
    const float* Wk = (const float*)d_in[3];
    const float* bk = (const float*)d_in[4];
    const float* Wv = (const float*)d_in[5];
    const float* bv = (const float*)d_in[6];
    const float* Wo = (const float*)d_in[7];
    const float* bo = (const float*)d_in[8];
    float* out = (float*)d_out;

    dim3 gp((TOK * DD / 4 + 255) / 256, 5);
    prep_kernel<<<gp, 256>>>(x, Wq, Wk, Wv, Wo);

    dim3 gq(TOK / 128, DD / 128, 3);
    qkv_kernel<<<gq, 256>>>(bq, bk, bv);

    dim3 ga(SS / 64, BHN);
    attn_kernel<<<ga, 128>>>();

    dim3 go(TOK / 128, DD / 128);
    oproj_kernel<<<go, 256>>>(bo, out);
}

// round 7
// speedup vs baseline: 3.1554x; 1.1598x over previous
#include <cuda_runtime.h>
#include <cuda_fp16.h>
#include <cstdint>

#define BB 8
#define SS 1024
#define DD 768
#define HH 16
#define HD 48
#define TOK (BB*SS)          // 8192
#define BHN (BB*HH)          // 128

// Static scratch (half precision)
__device__ __align__(256) __half g_xh[TOK*DD];
__device__ __align__(256) __half g_wh[4][DD*DD];     // Wq,Wk,Wv,Wo
__device__ __align__(256) __half g_qh[BHN*SS*HD];
__device__ __align__(256) __half g_kh[BHN*SS*HD];
__device__ __align__(256) __half g_vh[BHN*SS*HD];
__device__ __align__(256) __half g_aoh[TOK*DD];

// ---------------------------------------------------------------------------
// PTX helpers
// ---------------------------------------------------------------------------
__device__ __forceinline__ void ldm_x4(uint32_t r[4], const __half* p) {
    uint32_t a = (uint32_t)__cvta_generic_to_shared(p);
    asm volatile("ldmatrix.sync.aligned.m8n8.x4.shared.b16 {%0,%1,%2,%3}, [%4];"
                 : "=r"(r[0]), "=r"(r[1]), "=r"(r[2]), "=r"(r[3]) : "r"(a));
}
__device__ __forceinline__ void ldm_x4t(uint32_t r[4], const __half* p) {
    uint32_t a = (uint32_t)__cvta_generic_to_shared(p);
    asm volatile("ldmatrix.sync.aligned.m8n8.x4.trans.shared.b16 {%0,%1,%2,%3}, [%4];"
                 : "=r"(r[0]), "=r"(r[1]), "=r"(r[2]), "=r"(r[3]) : "r"(a));
}
__device__ __forceinline__ void mma16(float c[4], const uint32_t a[4],
                                      uint32_t b0, uint32_t b1) {
    asm volatile("mma.sync.aligned.m16n8k16.row.col.f32.f16.f16.f32 "
                 "{%0,%1,%2,%3}, {%4,%5,%6,%7}, {%8,%9}, {%0,%1,%2,%3};"
                 : "+f"(c[0]), "+f"(c[1]), "+f"(c[2]), "+f"(c[3])
                 : "r"(a[0]), "r"(a[1]), "r"(a[2]), "r"(a[3]), "r"(b0), "r"(b1));
}
__device__ __forceinline__ void cpa16(__half* dst, const __half* src) {
    uint32_t d = (uint32_t)__cvta_generic_to_shared(dst);
    asm volatile("cp.async.cg.shared.global [%0], [%1], 16;" :: "r"(d), "l"(src));
}
#define CP_COMMIT() asm volatile("cp.async.commit_group;")
#define CP_WAIT(N)  asm volatile("cp.async.wait_group %0;" :: "n"(N))

// ---------------------------------------------------------------------------
// Prep: convert x and the 4 weight matrices to half (rn rounding)
// ---------------------------------------------------------------------------
__global__ void prep_kernel(const float* __restrict__ x,
                            const float* __restrict__ Wq, const float* __restrict__ Wk,
                            const float* __restrict__ Wv, const float* __restrict__ Wo)
{
    const int y = blockIdx.y;
    const float* src; __half* dst; int n;
    if (y == 0)      { src = x;  dst = g_xh;     n = TOK * DD; }
    else             { src = (y == 1) ? Wq : (y == 2) ? Wk : (y == 3) ? Wv : Wo;
                       dst = g_wh[y - 1];        n = DD * DD; }
    int idx = (blockIdx.x * 256 + threadIdx.x) * 4;
    if (idx < n) {
        float4 v = *reinterpret_cast<const float4*>(src + idx);
        *reinterpret_cast<__half2*>(dst + idx)     = __floats2half2_rn(v.x, v.y);
        *reinterpret_cast<__half2*>(dst + idx + 2) = __floats2half2_rn(v.z, v.w);
    }
}

// ---------------------------------------------------------------------------
// fp16 GEMM: C[128x128] = A[*,768] @ W[768,768]. 256 thr = 8 warps.
// Warp tile 64x32, BK=32, 3-stage cp.async, ONE __syncthreads per chunk.
// As stride 40 halfs (80B), Bs stride 136 halfs (272B) -> conflict-free ldmatrix.
// ---------------------------------------------------------------------------
#define GST (128 * 40 + 32 * 136)          // halfs per stage (9472)
#define GEMM_SMEM_BYTES (3 * GST * 2)      // 56832 B
#define NCHUNK (DD / 32)                   // 24

__device__ __forceinline__ void gemm_load(__half* dsm, int st,
                                          const __half* __restrict__ A,
                                          const __half* __restrict__ W,
                                          int m0, int n0, int kt)
{
    __half* As = dsm + st * GST;
    __half* Bs = As + 128 * 40;
    const int tid = threadIdx.x;
    const int k0c = kt * 32;
    #pragma unroll
    for (int i = 0; i < 2; ++i) {
        int idx = tid + i * 256;
        int row = idx >> 2, cc = (idx & 3) * 8;
        cpa16(&As[row * 40 + cc], &A[(size_t)(m0 + row) * DD + k0c + cc]);
    }
    #pragma unroll
    for (int i = 0; i < 2; ++i) {
        int idx = tid + i * 256;
        int row = idx >> 4, cc = (idx & 15) * 8;
        cpa16(&Bs[row * 136 + cc], &W[(size_t)(k0c + row) * DD + n0 + cc]);
    }
}

__device__ __forceinline__ void gemm_compute(__half* dsm, int st,
                                             float acc[4][4][4])
{
    const __half* As = dsm + st * GST;
    const __half* Bs = As + 128 * 40;
    const int lane = threadIdx.x & 31, warp = threadIdx.x >> 5;
    const int wm = (warp >> 2) * 64, wn = (warp & 3) * 32;
    const int lr  = lane & 7;
    const int lk8 = ((lane >> 3) & 1) * 8;
    const int lh8 = (lane >> 4) * 8;
    #pragma unroll
    for (int ks = 0; ks < 2; ++ks) {
        const int k0 = ks * 16;
        uint32_t a[4][4], b[2][4];
        #pragma unroll
        for (int mi = 0; mi < 4; ++mi)
            ldm_x4(a[mi], &As[(wm + mi * 16 + lr + lk8) * 40 + k0 + lh8]);
        #pragma unroll
        for (int nh = 0; nh < 2; ++nh)
            ldm_x4t(b[nh], &Bs[(k0 + lr + lk8) * 136 + wn + nh * 16 + lh8]);
        #pragma unroll
        for (int mi = 0; mi < 4; ++mi)
            #pragma unroll
            for (int ni = 0; ni < 4; ++ni)
                mma16(acc[mi][ni], a[mi], b[ni >> 1][(ni & 1) * 2],
                      b[ni >> 1][(ni & 1) * 2 + 1]);
    }
}

// 3-stage mainloop: iteration kt waits for chunk kt (<=1 group pending),
// computes stage kt%3, then issues chunk kt+2 into stage (kt-1)%3 (safe:
// sync(kt) ordered after all warps' compute(kt-1)).
#define GEMM_LOOP(Aptr, Wptr)                                             \
    gemm_load(dsm, 0, Aptr, Wptr, m0, n0, 0); CP_COMMIT();                \
    gemm_load(dsm, 1, Aptr, Wptr, m0, n0, 1); CP_COMMIT();                \
    for (int kt = 0; kt < NCHUNK; ++kt) {                                 \
        CP_WAIT(1);                                                       \
        __syncthreads();                                                  \
        gemm_compute(dsm, kt % 3, acc);                                   \
        if (kt + 2 < NCHUNK)                                              \
            gemm_load(dsm, (kt + 2) % 3, Aptr, Wptr, m0, n0, kt + 2);     \
        CP_COMMIT();                                                      \
    }

// ---------------------------------------------------------------------------
// QKV projection -> g_qh/g_kh/g_vh as [B*H][S][48] half
// ---------------------------------------------------------------------------
__global__ void __launch_bounds__(256, 2)
qkv_kernel(const float* __restrict__ bq, const float* __restrict__ bk,
           const float* __restrict__ bv)
{
    extern __shared__ __half dsm[];
    const int z = blockIdx.z;
    const __half* W    = g_wh[z];
    const float* bias  = (z == 0) ? bq : (z == 1) ? bk : bv;
    __half* out        = (z == 0) ? g_qh : (z == 1) ? g_kh : g_vh;

    float acc[4][4][4] = {};
    const int m0 = blockIdx.x * 128, n0 = blockIdx.y * 128;
    GEMM_LOOP(g_xh, W)

    const int lane = threadIdx.x & 31, warp = threadIdx.x >> 5;
    const int g = lane >> 2, tig = lane & 3;
    const int wm = (warp >> 2) * 64, wn = (warp & 3) * 32;
    #pragma unroll
    for (int mi = 0; mi < 4; ++mi)
        #pragma unroll
        for (int ni = 0; ni < 4; ++ni) {
            const int c = n0 + wn + ni * 8 + 2 * tig;
            const int h = c / HD, hd = c % HD;
            const float b0f = bias[c], b1f = bias[c + 1];
            #pragma unroll
            for (int hr = 0; hr < 2; ++hr) {
                int r = wm + mi * 16 + g + hr * 8;
                int t = m0 + r;
                int bb = t >> 10, ss = t & 1023;
                __half2 hv = __floats2half2_rn(acc[mi][ni][hr * 2] + b0f,
                                               acc[mi][ni][hr * 2 + 1] + b1f);
                *reinterpret_cast<__half2*>(
                    &out[(((size_t)(bb * HH + h)) * SS + ss) * HD + hd]) = hv;
            }
        }
}

// ---------------------------------------------------------------------------
// Output projection: g_aoh @ Wo + bo -> d_out (fp32)
// ---------------------------------------------------------------------------
__global__ void __launch_bounds__(256, 2)
oproj_kernel(const float* __restrict__ bo, float* __restrict__ out)
{
    extern __shared__ __half dsm[];
    float acc[4][4][4] = {};
    const int m0 = blockIdx.x * 128, n0 = blockIdx.y * 128;
    GEMM_LOOP(g_aoh, g_wh[3])

    const int lane = threadIdx.x & 31, warp = threadIdx.x >> 5;
    const int g = lane >> 2, tig = lane & 3;
    const int wm = (warp >> 2) * 64, wn = (warp & 3) * 32;
    #pragma unroll
    for (int mi = 0; mi < 4; ++mi)
        #pragma unroll
        for (int ni = 0; ni < 4; ++ni) {
            const int c = n0 + wn + ni * 8 + 2 * tig;
            const float b0f = bo[c], b1f = bo[c + 1];
            #pragma unroll
            for (int hr = 0; hr < 2; ++hr) {
                int r = m0 + wm + mi * 16 + g + hr * 8;
                float2 v = make_float2(acc[mi][ni][hr * 2] + b0f,
                                       acc[mi][ni][hr * 2 + 1] + b1f);
                *reinterpret_cast<float2*>(&out[(size_t)r * DD + c]) = v;
            }
        }
}

// ---------------------------------------------------------------------------
// Flash attention, fp16 mma. CTA = 256 thr (8 warps), q-tile 128, k-tile 64.
// Warp owns 16 rows x full width -> in-register online softmax.
// Dynamic smem: Qs[128][56], Ks[2][64][56], Vs[2][64][56], Ps[128][72] = 60KB
// ---------------------------------------------------------------------------
#define AQ_OFF   0                       // Qs: 128*56
#define AK_OFF   (128 * 56)              // Ks[2]: 2*64*56
#define AV_OFF   (AK_OFF + 2 * 64 * 56)  // Vs[2]
#define AP_OFF   (AV_OFF + 2 * 64 * 56)  // Ps: 128*72
#define ATTN_SMEM_BYTES ((AP_OFF + 128 * 72) * 2)

__global__ void __launch_bounds__(256, 2)
attn_kernel()
{
    extern __shared__ __half dsm[];
    __half* Qs = dsm + AQ_OFF;
    __half* Ps = dsm + AP_OFF;

    const int tid  = threadIdx.x;
    const int lane = tid & 31, warp = tid >> 5;
    const int g = lane >> 2, tig = lane & 3;
    const int bh = blockIdx.y, q0 = blockIdx.x * 128;
    const __half* qp = g_qh + (size_t)bh * SS * HD;
    const __half* kp = g_kh + (size_t)bh * SS * HD;
    const __half* vp = g_vh + (size_t)bh * SS * HD;

    // Q: 128 rows x 48 = 768 x 16B chunks; 3 per thread
    #pragma unroll
    for (int i = 0; i < 3; ++i) {
        int idx = tid + i * 256;
        int r = idx / 6, cc = (idx % 6) * 8;
        cpa16(&Qs[r * 56 + cc], &qp[(size_t)(q0 + r) * HD + cc]);
    }
    // K0/V0: 64 rows x 48 = 384 chunks each; thread covers idx tid (+256 if tid<128)
    {
        __half* Kb = dsm + AK_OFF;
        __half* Vb = dsm + AV_OFF;
        int r = tid / 6, cc = (tid % 6) * 8;
        cpa16(&Kb[r * 56 + cc], &kp[(size_t)r * HD + cc]);
        cpa16(&Vb[r * 56 + cc], &vp[(size_t)r * HD + cc]);
        if (tid < 128) {
            int idx = tid + 256;
            int r2 = idx / 6, c2 = (idx % 6) * 8;
            cpa16(&Kb[r2 * 56 + c2], &kp[(size_t)r2 * HD + c2]);
            cpa16(&Vb[r2 * 56 + c2], &vp[(size_t)r2 * HD + c2]);
        }
    }
    CP_COMMIT();

    const int wr  = warp * 16;
    const int lr  = lane & 7;
    const int lk8 = ((lane >> 3) & 1) * 8;
    const int lh8 = (lane >> 4) * 8;

    float o[6][4] = {};
    float mr0 = -1e30f, mr1 = -1e30f, l0 = 0.f, l1 = 0.f;
    const float sc = 0.14433756729740643f;   // 1/sqrt(48)

    for (int kt = 0; kt < SS / 64; ++kt) {
        if (kt < SS / 64 - 1) {
            const int nb = (kt + 1) & 1;
            __half* Kb = dsm + AK_OFF + nb * 64 * 56;
            __half* Vb = dsm + AV_OFF + nb * 64 * 56;
            const size_t rb = (size_t)(kt + 1) * 64;
            int r = tid / 6, cc = (tid % 6) * 8;
            cpa16(&Kb[r * 56 + cc], &kp[(rb + r) * HD + cc]);
            cpa16(&Vb[r * 56 + cc], &vp[(rb + r) * HD + cc]);
            if (tid < 128) {
                int idx = tid + 256;
                int r2 = idx / 6, c2 = (idx % 6) * 8;
                cpa16(&Kb[r2 * 56 + c2], &kp[(rb + r2) * HD + c2]);
                cpa16(&Vb[r2 * 56 + c2], &vp[(rb + r2) * HD + c2]);
            }
            CP_COMMIT(); CP_WAIT(1);
        } else CP_WAIT(0);
        __syncthreads();

        const __half* Kb = dsm + AK_OFF + (kt & 1) * 64 * 56;
        const __half* Vb = dsm + AV_OFF + (kt & 1) * 64 * 56;

        // Scores: warp rows wr..wr+15 x 64 cols, K=48 (3 k16-steps)
        float s[8][4] = {};
        #pragma unroll
        for (int ks = 0; ks < 3; ++ks) {
            const int k0 = ks * 16;
            uint32_t a[4];
            ldm_x4(a, &Qs[(wr + lr + lk8) * 56 + k0 + lh8]);
            #pragma unroll
            for (int nh = 0; nh < 4; ++nh) {
                uint32_t b[4];
                ldm_x4(b, &Kb[(nh * 16 + lr + (lane >> 4) * 8) * 56 + k0 + lk8]);
                mma16(s[2 * nh],     a, b[0], b[1]);
                mma16(s[2 * nh + 1], a, b[2], b[3]);
            }
        }

        // In-register online softmax (rows g, g+8 of this warp)
        float mx0 = -1e30f, mx1 = -1e30f;
        #pragma unroll
        for (int nb = 0; nb < 8; ++nb) {
            mx0 = fmaxf(mx0, fmaxf(s[nb][0], s[nb][1]));
            mx1 = fmaxf(mx1, fmaxf(s[nb][2], s[nb][3]));
        }
        mx0 = fmaxf(mx0, __shfl_xor_sync(0xffffffffu, mx0, 1));
        mx0 = fmaxf(mx0, __shfl_xor_sync(0xffffffffu, mx0, 2));
        mx1 = fmaxf(mx1, __shfl_xor_sync(0xffffffffu, mx1, 1));
        mx1 = fmaxf(mx1, __shfl_xor_sync(0xffffffffu, mx1, 2));
        const float mn0 = fmaxf(mr0, mx0), mn1 = fmaxf(mr1, mx1);
        const float corr0 = __expf((mr0 - mn0) * sc);
        const float corr1 = __expf((mr1 - mn1) * sc);
        mr0 = mn0; mr1 = mn1;

        float sum0 = 0.f, sum1 = 0.f;
        #pragma unroll
        for (int nb = 0; nb < 8; ++nb) {
            float p0 = __expf((s[nb][0] - mn0) * sc);
            float p1 = __expf((s[nb][1] - mn0) * sc);
            float p2 = __expf((s[nb][2] - mn1) * sc);
            float p3 = __expf((s[nb][3] - mn1) * sc);
            sum0 += p0 + p1; sum1 += p2 + p3;
            *reinterpret_cast<__half2*>(&Ps[(wr + g) * 72 + nb * 8 + 2 * tig]) =
                __floats2half2_rn(p0, p1);
            *reinterpret_cast<__half2*>(&Ps[(wr + g + 8) * 72 + nb * 8 + 2 * tig]) =
                __floats2half2_rn(p2, p3);
        }
        sum0 += __shfl_xor_sync(0xffffffffu, sum0, 1);
        sum0 += __shfl_xor_sync(0xffffffffu, sum0, 2);
        sum1 += __shfl_xor_sync(0xffffffffu, sum1, 1);
        sum1 += __shfl_xor_sync(0xffffffffu, sum1, 2);
        l0 = l0 * corr0 + sum0;
        l1 = l1 * corr1 + sum1;

        #pragma unroll
        for (int nb = 0; nb < 6; ++nb) {
            o[nb][0] *= corr0; o[nb][1] *= corr0;
            o[nb][2] *= corr1; o[nb][3] *= corr1;
        }
        __syncwarp();   // P (this warp's rows) visible within warp

        // PV: warp rows x 48 cols, K=64 (4 k16-steps)
        #pragma unroll
        for (int ks = 0; ks < 4; ++ks) {
            const int k0 = ks * 16;
            uint32_t a[4];
            ldm_x4(a, &Ps[(wr + lr + lk8) * 72 + k0 + lh8]);
            #pragma unroll
            for (int nh = 0; nh < 3; ++nh) {
                uint32_t b[4];
                ldm_x4t(b, &Vb[(k0 + lr + lk8) * 56 + nh * 16 + lh8]);
                mma16(o[2 * nh],     a, b[0], b[1]);
                mma16(o[2 * nh + 1], a, b[2], b[3]);
            }
        }
        __syncthreads();
    }

    // Epilogue: normalize, write g_aoh [B*S][768]
    const float li0 = 1.f / l0, li1 = 1.f / l1;
    const int bb = bh >> 4, h = bh & 15;
    const int r0 = q0 + wr + g, r1 = r0 + 8;
    #pragma unroll
    for (int nb = 0; nb < 6; ++nb) {
        int c = h * HD + nb * 8 + 2 * tig;
        *reinterpret_cast<__half2*>(&g_aoh[((size_t)(bb * SS + r0)) * DD + c]) =
            __floats2half2_rn(o[nb][0] * li0, o[nb][1] * li0);
        *reinterpret_cast<__half2*>(&g_aoh[((size_t)(bb * SS + r1)) * DD + c]) =
            __floats2half2_rn(o[nb][2] * li1, o[nb][3] * li1);
    }
}

// ---------------------------------------------------------------------------
extern "C" void kernel_launch(void* const* d_in, const int* in_sizes, int n_in,
                              void* d_out, int out_size)
{
    const float* x  = (const float*)d_in[0];
    const float* Wq = (const float*)d_in[1];
    const float* bq = (const float*)d_in[2];
    const float* Wk = (const float*)d_in[3];
    const float* bk = (const float*)d_in[4];
    const float* Wv = (const float*)d_in[5];
    const float* bv = (const float*)d_in[6];
    const float* Wo = (const float*)d_in[7];
    const float* bo = (const float*)d_in[8];
    float* out = (float*)d_out;

    static bool attr_done = false;
    if (!attr_done) {
        cudaFuncSetAttribute(qkv_kernel,
            cudaFuncAttributeMaxDynamicSharedMemorySize, GEMM_SMEM_BYTES);
        cudaFuncSetAttribute(oproj_kernel,
            cudaFuncAttributeMaxDynamicSharedMemorySize, GEMM_SMEM_BYTES);
        cudaFuncSetAttribute(attn_kernel,
            cudaFuncAttributeMaxDynamicSharedMemorySize, ATTN_SMEM_BYTES);
        attr_done = true;
    }

    dim3 gp((TOK * DD / 4 + 255) / 256, 5);
    prep_kernel<<<gp, 256>>>(x, Wq, Wk, Wv, Wo);

    dim3 gq(TOK / 128, DD / 128, 3);
    qkv_kernel<<<gq, 256, GEMM_SMEM_BYTES>>>(bq, bk, bv);

    dim3 ga(SS / 128, BHN);
    attn_kernel<<<ga, 256, ATTN_SMEM_BYTES>>>();

    dim3 go(TOK / 128, DD / 128);
    oproj_kernel<<<go, 256, GEMM_SMEM_BYTES>>>(bo, out);
}

// round 9
// speedup vs baseline: 3.8459x; 1.2188x over previous
#include <cuda_runtime.h>
#include <cuda_fp16.h>
#include <cstdint>

#define BB 8
#define SS 1024
#define DD 768
#define HH 16
#define HD 48
#define TOK (BB*SS)          // 8192
#define BHN (BB*HH)          // 128

// Static scratch (half precision)
__device__ __align__(256) __half g_xh[TOK*DD];
__device__ __align__(256) __half g_wh[4][DD*DD];     // Wq,Wk,Wv,Wo
__device__ __align__(256) __half g_qh[BHN*SS*HD];    // Q pre-scaled by 1/sqrt(48)*log2(e)
__device__ __align__(256) __half g_kh[BHN*SS*HD];
__device__ __align__(256) __half g_vh[BHN*SS*HD];
__device__ __align__(256) __half g_aoh[TOK*DD];

// 1/sqrt(48) * log2(e) — folded into Q so softmax exp is a bare ex2
#define QSCALE 0.20824705232299967f

// ---------------------------------------------------------------------------
// PTX helpers
// ---------------------------------------------------------------------------
__device__ __forceinline__ void ldm_x4(uint32_t r[4], const __half* p) {
    uint32_t a = (uint32_t)__cvta_generic_to_shared(p);
    asm volatile("ldmatrix.sync.aligned.m8n8.x4.shared.b16 {%0,%1,%2,%3}, [%4];"
                 : "=r"(r[0]), "=r"(r[1]), "=r"(r[2]), "=r"(r[3]) : "r"(a));
}
__device__ __forceinline__ void ldm_x4t(uint32_t r[4], const __half* p) {
    uint32_t a = (uint32_t)__cvta_generic_to_shared(p);
    asm volatile("ldmatrix.sync.aligned.m8n8.x4.trans.shared.b16 {%0,%1,%2,%3}, [%4];"
                 : "=r"(r[0]), "=r"(r[1]), "=r"(r[2]), "=r"(r[3]) : "r"(a));
}
__device__ __forceinline__ void mma16(float c[4], const uint32_t a[4],
                                      uint32_t b0, uint32_t b1) {
    asm volatile("mma.sync.aligned.m16n8k16.row.col.f32.f16.f16.f32 "
                 "{%0,%1,%2,%3}, {%4,%5,%6,%7}, {%8,%9}, {%0,%1,%2,%3};"
                 : "+f"(c[0]), "+f"(c[1]), "+f"(c[2]), "+f"(c[3])
                 : "r"(a[0]), "r"(a[1]), "r"(a[2]), "r"(a[3]), "r"(b0), "r"(b1));
}
__device__ __forceinline__ void cpa16(__half* dst, const __half* src) {
    uint32_t d = (uint32_t)__cvta_generic_to_shared(dst);
    asm volatile("cp.async.cg.shared.global [%0], [%1], 16;" :: "r"(d), "l"(src));
}
#define CP_COMMIT() asm volatile("cp.async.commit_group;")
#define CP_WAIT(N)  asm volatile("cp.async.wait_group %0;" :: "n"(N))

__device__ __forceinline__ float ex2(float x) {
    float y;
    asm("ex2.approx.ftz.f32 %0, %1;" : "=f"(y) : "f"(x));
    return y;
}
__device__ __forceinline__ uint32_t packh2(float lo, float hi) {
    __half2 h = __floats2half2_rn(lo, hi);
    return *reinterpret_cast<uint32_t*>(&h);
}

// ---------------------------------------------------------------------------
// Prep: convert x and the 4 weight matrices to half
// ---------------------------------------------------------------------------
__global__ void prep_kernel(const float* __restrict__ x,
                            const float* __restrict__ Wq, const float* __restrict__ Wk,
                            const float* __restrict__ Wv, const float* __restrict__ Wo)
{
    const int y = blockIdx.y;
    const float* src; __half* dst; int n;
    if (y == 0)      { src = x;  dst = g_xh;     n = TOK * DD; }
    else             { src = (y == 1) ? Wq : (y == 2) ? Wk : (y == 3) ? Wv : Wo;
                       dst = g_wh[y - 1];        n = DD * DD; }
    int idx = (blockIdx.x * 256 + threadIdx.x) * 4;
    if (idx < n) {
        float4 v = *reinterpret_cast<const float4*>(src + idx);
        *reinterpret_cast<__half2*>(dst + idx)     = __floats2half2_rn(v.x, v.y);
        *reinterpret_cast<__half2*>(dst + idx + 2) = __floats2half2_rn(v.z, v.w);
    }
}

// ---------------------------------------------------------------------------
// fp16 GEMM: C[128x128] = A[*,768] @ W[768,768]. 256 thr = 8 warps.
// Warp tile 64x32, BK=32, 3-stage cp.async, one __syncthreads per chunk.
// ---------------------------------------------------------------------------
#define GST (128 * 40 + 32 * 136)          // halfs per stage (9472)
#define GEMM_SMEM_BYTES (3 * GST * 2)      // 56832 B
#define NCHUNK (DD / 32)                   // 24

__device__ __forceinline__ void gemm_load(__half* dsm, int st,
                                          const __half* __restrict__ A,
                                          const __half* __restrict__ W,
                                          int m0, int n0, int kt)
{
    __half* As = dsm + st * GST;
    __half* Bs = As + 128 * 40;
    const int tid = threadIdx.x;
    const int k0c = kt * 32;
    #pragma unroll
    for (int i = 0; i < 2; ++i) {
        int idx = tid + i * 256;
        int row = idx >> 2, cc = (idx & 3) * 8;
        cpa16(&As[row * 40 + cc], &A[(size_t)(m0 + row) * DD + k0c + cc]);
    }
    #pragma unroll
    for (int i = 0; i < 2; ++i) {
        int idx = tid + i * 256;
        int row = idx >> 4, cc = (idx & 15) * 8;
        cpa16(&Bs[row * 136 + cc], &W[(size_t)(k0c + row) * DD + n0 + cc]);
    }
}

__device__ __forceinline__ void gemm_compute(__half* dsm, int st,
                                             float acc[4][4][4])
{
    const __half* As = dsm + st * GST;
    const __half* Bs = As + 128 * 40;
    const int lane = threadIdx.x & 31, warp = threadIdx.x >> 5;
    const int wm = (warp >> 2) * 64, wn = (warp & 3) * 32;
    const int lr  = lane & 7;
    const int lk8 = ((lane >> 3) & 1) * 8;
    const int lh8 = (lane >> 4) * 8;
    #pragma unroll
    for (int ks = 0; ks < 2; ++ks) {
        const int k0 = ks * 16;
        uint32_t a[4][4], b[2][4];
        #pragma unroll
        for (int mi = 0; mi < 4; ++mi)
            ldm_x4(a[mi], &As[(wm + mi * 16 + lr + lk8) * 40 + k0 + lh8]);
        #pragma unroll
        for (int nh = 0; nh < 2; ++nh)
            ldm_x4t(b[nh], &Bs[(k0 + lr + lk8) * 136 + wn + nh * 16 + lh8]);
        #pragma unroll
        for (int mi = 0; mi < 4; ++mi)
            #pragma unroll
            for (int ni = 0; ni < 4; ++ni)
                mma16(acc[mi][ni], a[mi], b[ni >> 1][(ni & 1) * 2],
                      b[ni >> 1][(ni & 1) * 2 + 1]);
    }
}

#define GEMM_LOOP(Aptr, Wptr)                                             \
    gemm_load(dsm, 0, Aptr, Wptr, m0, n0, 0); CP_COMMIT();                \
    gemm_load(dsm, 1, Aptr, Wptr, m0, n0, 1); CP_COMMIT();                \
    for (int kt = 0; kt < NCHUNK; ++kt) {                                 \
        CP_WAIT(1);                                                       \
        __syncthreads();                                                  \
        gemm_compute(dsm, kt % 3, acc);                                   \
        if (kt + 2 < NCHUNK)                                              \
            gemm_load(dsm, (kt + 2) % 3, Aptr, Wptr, m0, n0, kt + 2);     \
        CP_COMMIT();                                                      \
    }

// ---------------------------------------------------------------------------
// QKV projection -> g_qh/g_kh/g_vh as [B*H][S][48] half (Q pre-scaled)
// ---------------------------------------------------------------------------
__global__ void __launch_bounds__(256, 2)
qkv_kernel(const float* __restrict__ bq, const float* __restrict__ bk,
           const float* __restrict__ bv)
{
    extern __shared__ __half dsm[];
    const int z = blockIdx.z;
    const __half* W    = g_wh[z];
    const float* bias  = (z == 0) ? bq : (z == 1) ? bk : bv;
    __half* out        = (z == 0) ? g_qh : (z == 1) ? g_kh : g_vh;
    const float oscale = (z == 0) ? QSCALE : 1.0f;

    float acc[4][4][4] = {};
    const int m0 = blockIdx.x * 128, n0 = blockIdx.y * 128;
    GEMM_LOOP(g_xh, W)

    const int lane = threadIdx.x & 31, warp = threadIdx.x >> 5;
    const int g = lane >> 2, tig = lane & 3;
    const int wm = (warp >> 2) * 64, wn = (warp & 3) * 32;
    #pragma unroll
    for (int mi = 0; mi < 4; ++mi)
        #pragma unroll
        for (int ni = 0; ni < 4; ++ni) {
            const int c = n0 + wn + ni * 8 + 2 * tig;
            const int h = c / HD, hd = c % HD;
            const float b0f = bias[c], b1f = bias[c + 1];
            #pragma unroll
            for (int hr = 0; hr < 2; ++hr) {
                int r = wm + mi * 16 + g + hr * 8;
                int t = m0 + r;
                int bb = t >> 10, ss = t & 1023;
                __half2 hv = __floats2half2_rn(
                    (acc[mi][ni][hr * 2] + b0f) * oscale,
                    (acc[mi][ni][hr * 2 + 1] + b1f) * oscale);
                *reinterpret_cast<__half2*>(
                    &out[(((size_t)(bb * HH + h)) * SS + ss) * HD + hd]) = hv;
            }
        }
}

// ---------------------------------------------------------------------------
// Output projection: g_aoh @ Wo + bo -> d_out (fp32)
// ---------------------------------------------------------------------------
__global__ void __launch_bounds__(256, 2)
oproj_kernel(const float* __restrict__ bo, float* __restrict__ out)
{
    extern __shared__ __half dsm[];
    float acc[4][4][4] = {};
    const int m0 = blockIdx.x * 128, n0 = blockIdx.y * 128;
    GEMM_LOOP(g_aoh, g_wh[3])

    const int lane = threadIdx.x & 31, warp = threadIdx.x >> 5;
    const int g = lane >> 2, tig = lane & 3;
    const int wm = (warp >> 2) * 64, wn = (warp & 3) * 32;
    #pragma unroll
    for (int mi = 0; mi < 4; ++mi)
        #pragma unroll
        for (int ni = 0; ni < 4; ++ni) {
            const int c = n0 + wn + ni * 8 + 2 * tig;
            const float b0f = bo[c], b1f = bo[c + 1];
            #pragma unroll
            for (int hr = 0; hr < 2; ++hr) {
                int r = m0 + wm + mi * 16 + g + hr * 8;
                float2 v = make_float2(acc[mi][ni][hr * 2] + b0f,
                                       acc[mi][ni][hr * 2 + 1] + b1f);
                *reinterpret_cast<float2*>(&out[(size_t)r * DD + c]) = v;
            }
        }
}

// ---------------------------------------------------------------------------
// Flash attention: register-passed P, no online max, 3-stage K/V cp.async.
// CTA = 256 thr (8 warps), q-tile 128, k-tile 64. Warp = 16 rows x full width.
// Smem: Qs[128][56] + 3 x (K[64][56] + V[64][56]) = 57344 B. 1 sync per tile,
// ordered wait -> barrier -> compute (cross-thread cp.async visibility).
// ---------------------------------------------------------------------------
#define AQ_OFF   0                       // Qs: 128*56
#define AKV_OFF  (128 * 56)              // 3 stages of (K 64*56 + V 64*56)
#define KVST     (2 * 64 * 56)           // halfs per stage
#define ATTN_SMEM_BYTES ((128 * 56 + 3 * KVST) * 2)   // 57344
#define NT (SS / 64)                     // 16

__device__ __forceinline__ void attn_load_kv(__half* dsm, int st,
                                             const __half* kp, const __half* vp,
                                             int kt)
{
    __half* Kb = dsm + AKV_OFF + st * KVST;
    __half* Vb = Kb + 64 * 56;
    const int tid = threadIdx.x;
    const size_t rb = (size_t)kt * 64;
    int r = tid / 6, cc = (tid % 6) * 8;
    cpa16(&Kb[r * 56 + cc], &kp[(rb + r) * HD + cc]);
    cpa16(&Vb[r * 56 + cc], &vp[(rb + r) * HD + cc]);
    if (tid < 128) {
        int idx = tid + 256;
        int r2 = idx / 6, c2 = (idx % 6) * 8;
        cpa16(&Kb[r2 * 56 + c2], &kp[(rb + r2) * HD + c2]);
        cpa16(&Vb[r2 * 56 + c2], &vp[(rb + r2) * HD + c2]);
    }
}

__global__ void __launch_bounds__(256, 2)
attn_kernel()
{
    extern __shared__ __half dsm[];
    __half* Qs = dsm + AQ_OFF;

    const int tid  = threadIdx.x;
    const int lane = tid & 31, warp = tid >> 5;
    const int g = lane >> 2, tig = lane & 3;
    const int bh = blockIdx.y, q0 = blockIdx.x * 128;
    const __half* qp = g_qh + (size_t)bh * SS * HD;
    const __half* kp = g_kh + (size_t)bh * SS * HD;
    const __half* vp = g_vh + (size_t)bh * SS * HD;

    // Prologue: Q (768 x 16B chunks, 3/thread) + KV0 -> G0 ; KV1 -> G1
    #pragma unroll
    for (int i = 0; i < 3; ++i) {
        int idx = tid + i * 256;
        int r = idx / 6, cc = (idx % 6) * 8;
        cpa16(&Qs[r * 56 + cc], &qp[(size_t)(q0 + r) * HD + cc]);
    }
    attn_load_kv(dsm, 0, kp, vp, 0); CP_COMMIT();
    attn_load_kv(dsm, 1, kp, vp, 1); CP_COMMIT();

    const int wr  = warp * 16;
    const int lr  = lane & 7;
    const int lk8 = ((lane >> 3) & 1) * 8;
    const int lh8 = (lane >> 4) * 8;

    float o[6][4] = {};
    float l0 = 0.f, l1 = 0.f;

    for (int kt = 0; kt < NT; ++kt) {
        CP_WAIT(1);          // own G_kt complete
        __syncthreads();     // everyone's G_kt visible; compute kt-1 done by all
        if (kt + 2 < NT)
            attn_load_kv(dsm, (kt + 2) % 3, kp, vp, kt + 2);   // stage (kt-1)%3: free
        CP_COMMIT();

        const __half* Kb = dsm + AKV_OFF + (kt % 3) * KVST;
        const __half* Vb = Kb + 64 * 56;

        // Scores: warp rows wr..wr+15 x 64 cols, K=48
        float s[8][4] = {};
        #pragma unroll
        for (int ks = 0; ks < 3; ++ks) {
            const int k0 = ks * 16;
            uint32_t a[4];
            ldm_x4(a, &Qs[(wr + lr + lk8) * 56 + k0 + lh8]);
            #pragma unroll
            for (int nh = 0; nh < 4; ++nh) {
                uint32_t b[4];
                ldm_x4(b, &Kb[(nh * 16 + lr + (lane >> 4) * 8) * 56 + k0 + lk8]);
                mma16(s[2 * nh],     a, b[0], b[1]);
                mma16(s[2 * nh + 1], a, b[2], b[3]);
            }
        }

        // exp + pack straight into PV A-fragments (score C-frag == PV A-frag)
        uint32_t ap[4][4];
        float sum0 = 0.f, sum1 = 0.f;
        #pragma unroll
        for (int nb = 0; nb < 8; ++nb) {
            float p0 = ex2(s[nb][0]);
            float p1 = ex2(s[nb][1]);
            float p2 = ex2(s[nb][2]);
            float p3 = ex2(s[nb][3]);
            sum0 += p0 + p1; sum1 += p2 + p3;
            ap[nb >> 1][(nb & 1) * 2 + 0] = packh2(p0, p1);
            ap[nb >> 1][(nb & 1) * 2 + 1] = packh2(p2, p3);
        }
        l0 += sum0; l1 += sum1;

        // PV: warp rows x 48 cols, K=64; A from registers
        #pragma unroll
        for (int ks = 0; ks < 4; ++ks) {
            const int k0 = ks * 16;
            #pragma unroll
            for (int nh = 0; nh < 3; ++nh) {
                uint32_t b[4];
                ldm_x4t(b, &Vb[(k0 + lr + lk8) * 56 + nh * 16 + lh8]);
                mma16(o[2 * nh],     ap[ks], b[0], b[1]);
                mma16(o[2 * nh + 1], ap[ks], b[2], b[3]);
            }
        }
    }

    // Reduce l across the 4 tig lanes, normalize, store
    l0 += __shfl_xor_sync(0xffffffffu, l0, 1);
    l0 += __shfl_xor_sync(0xffffffffu, l0, 2);
    l1 += __shfl_xor_sync(0xffffffffu, l1, 1);
    l1 += __shfl_xor_sync(0xffffffffu, l1, 2);
    const float li0 = 1.f / l0, li1 = 1.f / l1;
    const int bb = bh >> 4, h = bh & 15;
    const int r0 = q0 + wr + g, r1 = r0 + 8;
    #pragma unroll
    for (int nb = 0; nb < 6; ++nb) {
        int c = h * HD + nb * 8 + 2 * tig;
        *reinterpret_cast<__half2*>(&g_aoh[((size_t)(bb * SS + r0)) * DD + c]) =
            __floats2half2_rn(o[nb][0] * li0, o[nb][1] * li0);
        *reinterpret_cast<__half2*>(&g_aoh[((size_t)(bb * SS + r1)) * DD + c]) =
            __floats2half2_rn(o[nb][2] * li1, o[nb][3] * li1);
    }
}

// ---------------------------------------------------------------------------
extern "C" void kernel_launch(void* const* d_in, const int* in_sizes, int n_in,
                              void* d_out, int out_size)
{
    const float* x  = (const float*)d_in[0];
    const float* Wq = (const float*)d_in[1];
    const float* bq = (const float*)d_in[2];
    const float* Wk = (const float*)d_in[3];
    const float* bk = (const float*)d_in[4];
    const float* Wv = (const float*)d_in[5];
    const float* bv = (const float*)d_in[6];
    const float* Wo = (const float*)d_in[7];
    const float* bo = (const float*)d_in[8];
    float* out = (float*)d_out;

    static bool attr_done = false;
    if (!attr_done) {
        cudaFuncSetAttribute(qkv_kernel,
            cudaFuncAttributeMaxDynamicSharedMemorySize, GEMM_SMEM_BYTES);
        cudaFuncSetAttribute(oproj_kernel,
            cudaFuncAttributeMaxDynamicSharedMemorySize, GEMM_SMEM_BYTES);
        cudaFuncSetAttribute(attn_kernel,
            cudaFuncAttributeMaxDynamicSharedMemorySize, ATTN_SMEM_BYTES);
        attr_done = true;
    }

    dim3 gp((TOK * DD / 4 + 255) / 256, 5);
    prep_kernel<<<gp, 256>>>(x, Wq, Wk, Wv, Wo);

    dim3 gq(TOK / 128, DD / 128, 3);
    qkv_kernel<<<gq, 256, GEMM_SMEM_BYTES>>>(bq, bk, bv);

    dim3 ga(SS / 128, BHN);
    attn_kernel<<<ga, 256, ATTN_SMEM_BYTES>>>();

    dim3 go(TOK / 128, DD / 128);
    oproj_kernel<<<go, 256, GEMM_SMEM_BYTES>>>(bo, out);
}